// round 2
// baseline (speedup 1.0000x reference)
#include <cuda_runtime.h>
#include <cuda_bf16.h>
#include <cstdint>

// Problem constants (fixed shapes for this problem)
#define MAXN 100000
#define MAXE 1600000
#define DIM  64
#define MAXG 512
#define SCAN_CHUNK 1024

// ---------------- scratch (static device globals; no allocation allowed) ----
__device__ int   g_cnt[MAXN];          // in-degree counts (excl self loop)
__device__ int   g_rowptr[MAXN + 1];   // CSR row pointers (by dst)
__device__ int   g_cursor[MAXN];       // scatter cursors
__device__ float g_dinv[MAXN];         // deg^-0.5 (deg incl self loop)
__device__ int   g_esrc[MAXE];         // CSR column (src) indices
__device__ int   g_bsum[(MAXN + SCAN_CHUNK - 1) / SCAN_CHUNK + 1];
__device__ float g_z[(size_t)MAXN * DIM];   // z = dinv * (x @ W)
__device__ float g_xa[(size_t)MAXN * DIM];  // feature ping
__device__ float g_xb[(size_t)MAXN * DIM];  // feature pong
__device__ float g_hsum[MAXG * DIM];
__device__ float g_hmax[MAXG * DIM];
__device__ int   g_gcnt[MAXG];

// ---------------- CSR build ------------------------------------------------
__global__ void k_count(const int* __restrict__ dst, int e) {
    int i = blockIdx.x * blockDim.x + threadIdx.x;
    if (i < e) atomicAdd(&g_cnt[dst[i]], 1);
}

__global__ void k_scan1(int n) {  // per-1024-chunk sums
    int t = threadIdx.x;
    int base = blockIdx.x * SCAN_CHUNK + t * 4;
    int s = 0;
#pragma unroll
    for (int j = 0; j < 4; j++) if (base + j < n) s += g_cnt[base + j];
#pragma unroll
    for (int o = 16; o; o >>= 1) s += __shfl_down_sync(0xffffffffu, s, o);
    __shared__ int ws[8];
    if ((t & 31) == 0) ws[t >> 5] = s;
    __syncthreads();
    if (t == 0) {
        int tot = 0;
#pragma unroll
        for (int i = 0; i < 8; i++) tot += ws[i];
        g_bsum[blockIdx.x] = tot;
    }
}

__global__ void k_scan2(int nb, int n) {  // tiny serial scan of chunk sums
    int run = 0;
    for (int i = 0; i < nb; i++) { int v = g_bsum[i]; g_bsum[i] = run; run += v; }
    g_rowptr[n] = run;
}

__global__ void k_scan3(int n) {  // per-chunk exclusive scan -> rowptr/cursor
    int t = threadIdx.x;
    int lane = t & 31, wid = t >> 5;
    int base = blockIdx.x * SCAN_CHUNK + t * 4;
    int c0 = (base + 0 < n) ? g_cnt[base + 0] : 0;
    int c1 = (base + 1 < n) ? g_cnt[base + 1] : 0;
    int c2 = (base + 2 < n) ? g_cnt[base + 2] : 0;
    int c3 = (base + 3 < n) ? g_cnt[base + 3] : 0;
    int ts = c0 + c1 + c2 + c3;
    int x = ts;
#pragma unroll
    for (int o = 1; o < 32; o <<= 1) {
        int y = __shfl_up_sync(0xffffffffu, x, o);
        if (lane >= o) x += y;
    }
    int wex = x - ts;  // exclusive within warp
    __shared__ int warpsums[8];
    if (lane == 31) warpsums[wid] = x;
    __syncthreads();
    int woff = 0;
    for (int i = 0; i < wid; i++) woff += warpsums[i];
    int off = g_bsum[blockIdx.x] + woff + wex;
    if (base + 0 < n) { g_rowptr[base + 0] = off;             g_cursor[base + 0] = off; }
    if (base + 1 < n) { g_rowptr[base + 1] = off + c0;        g_cursor[base + 1] = off + c0; }
    if (base + 2 < n) { g_rowptr[base + 2] = off + c0 + c1;   g_cursor[base + 2] = off + c0 + c1; }
    if (base + 3 < n) { g_rowptr[base + 3] = off + c0 + c1 + c2; g_cursor[base + 3] = off + c0 + c1 + c2; }
}

__global__ void k_dinv(int n) {
    int i = blockIdx.x * blockDim.x + threadIdx.x;
    if (i < n) g_dinv[i] = rsqrtf((float)(g_cnt[i] + 1));  // +1 self loop
}

__global__ void k_scatter(const int* __restrict__ src, const int* __restrict__ dst, int e) {
    int i = blockIdx.x * blockDim.x + threadIdx.x;
    if (i < e) {
        int d = dst[i];
        int p = atomicAdd(&g_cursor[d], 1);
        g_esrc[p] = src[i];
    }
}

// ---------------- fused GEMM: z = dinv[i] * (x_i @ W) ----------------------
// block = 256 threads; block tile = 64 rows x 64 cols; thread = 1 row x 16 cols
__global__ void k_gemm(const float* __restrict__ X, const int* __restrict__ tokens,
                       const float* __restrict__ emb, const float* __restrict__ W,
                       float* __restrict__ Z, int n) {
    __shared__ float Ws[DIM * DIM];
    int t = threadIdx.x;
    for (int i = t; i < DIM * DIM; i += 256) Ws[i] = W[i];
    __syncthreads();
    int row = blockIdx.x * 64 + (t >> 2);
    if (row >= n) return;
    const float* xr = tokens ? (emb + (size_t)__ldg(tokens + row) * DIM)
                             : (X + (size_t)row * DIM);
    int cg = (t & 3) * 16;
    float acc[16];
#pragma unroll
    for (int j = 0; j < 16; j++) acc[j] = 0.f;
#pragma unroll
    for (int k = 0; k < DIM; k += 4) {
        float4 xv = *(const float4*)(xr + k);
#pragma unroll
        for (int kk = 0; kk < 4; kk++) {
            float xs = (&xv.x)[kk];
            const float4* w4 = (const float4*)(Ws + (k + kk) * DIM + cg);
            float4 w0 = w4[0], w1 = w4[1], w2 = w4[2], w3 = w4[3];
            acc[0]  = fmaf(xs, w0.x, acc[0]);  acc[1]  = fmaf(xs, w0.y, acc[1]);
            acc[2]  = fmaf(xs, w0.z, acc[2]);  acc[3]  = fmaf(xs, w0.w, acc[3]);
            acc[4]  = fmaf(xs, w1.x, acc[4]);  acc[5]  = fmaf(xs, w1.y, acc[5]);
            acc[6]  = fmaf(xs, w1.z, acc[6]);  acc[7]  = fmaf(xs, w1.w, acc[7]);
            acc[8]  = fmaf(xs, w2.x, acc[8]);  acc[9]  = fmaf(xs, w2.y, acc[9]);
            acc[10] = fmaf(xs, w2.z, acc[10]); acc[11] = fmaf(xs, w2.w, acc[11]);
            acc[12] = fmaf(xs, w3.x, acc[12]); acc[13] = fmaf(xs, w3.y, acc[13]);
            acc[14] = fmaf(xs, w3.z, acc[14]); acc[15] = fmaf(xs, w3.w, acc[15]);
        }
    }
    float dv = g_dinv[row];
    float* zr = Z + (size_t)row * DIM + cg;
#pragma unroll
    for (int j = 0; j < 16; j += 4) {
        float4 o;
        o.x = acc[j] * dv; o.y = acc[j + 1] * dv;
        o.z = acc[j + 2] * dv; o.w = acc[j + 3] * dv;
        *(float4*)(zr + j) = o;
    }
}

// ---------------- gather: x_out[i] = relu(dinv[i]*(z[i] + sum z[src]) + b) --
// warp per destination node; lane covers 2 feature dims as float2
__global__ void k_gather(const float* __restrict__ Z, const float* __restrict__ b,
                         float* __restrict__ Xo, int n) {
    int w = (int)((blockIdx.x * blockDim.x + threadIdx.x) >> 5);
    if (w >= n) return;
    int lane = threadIdx.x & 31;
    int beg = g_rowptr[w], end = g_rowptr[w + 1];
    const float2* zc = (const float2*)Z;        // node row = 32 float2
    float2 acc = zc[(size_t)w * 32 + lane];     // self loop
    for (int e0 = beg; e0 < end; e0 += 32) {
        int c = end - e0; if (c > 32) c = 32;
        int s = (lane < c) ? g_esrc[e0 + lane] : 0;
        int j = 0;
        for (; j + 4 <= c; j += 4) {
            int s0 = __shfl_sync(0xffffffffu, s, j);
            int s1 = __shfl_sync(0xffffffffu, s, j + 1);
            int s2 = __shfl_sync(0xffffffffu, s, j + 2);
            int s3 = __shfl_sync(0xffffffffu, s, j + 3);
            float2 v0 = zc[(size_t)s0 * 32 + lane];
            float2 v1 = zc[(size_t)s1 * 32 + lane];
            float2 v2 = zc[(size_t)s2 * 32 + lane];
            float2 v3 = zc[(size_t)s3 * 32 + lane];
            acc.x += (v0.x + v1.x) + (v2.x + v3.x);
            acc.y += (v0.y + v1.y) + (v2.y + v3.y);
        }
        for (; j < c; j++) {
            int sj = __shfl_sync(0xffffffffu, s, j);
            float2 v = zc[(size_t)sj * 32 + lane];
            acc.x += v.x; acc.y += v.y;
        }
    }
    float dv = g_dinv[w];
    int col = lane * 2;
    float2 o;
    o.x = fmaxf(fmaf(dv, acc.x, __ldg(b + col)),     0.f);
    o.y = fmaxf(fmaf(dv, acc.y, __ldg(b + col + 1)), 0.f);
    ((float2*)Xo)[(size_t)w * 32 + lane] = o;
}

// ---------------- pooling (batch sorted): run-accumulate, flush on boundary -
__global__ void k_pool(const float* __restrict__ X, const int* __restrict__ batch, int n) {
    int w = (int)((blockIdx.x * blockDim.x + threadIdx.x) >> 5);
    int lane = threadIdx.x & 31;
    int base = w * 32;
    if (base >= n) return;
    int myb = (base + lane < n) ? batch[base + lane] : 0;
    const float2* xc = (const float2*)X;
    float2 s = make_float2(0.f, 0.f), m = make_float2(0.f, 0.f);
    int curg = __shfl_sync(0xffffffffu, myb, 0);
    int rc = 0;
    for (int j = 0; j < 32; j++) {
        int node = base + j;
        if (node >= n) break;
        int g = __shfl_sync(0xffffffffu, myb, j);
        if (g != curg) {
            atomicAdd(&g_hsum[curg * DIM + lane * 2],     s.x);
            atomicAdd(&g_hsum[curg * DIM + lane * 2 + 1], s.y);
            atomicMax((int*)&g_hmax[curg * DIM + lane * 2],     __float_as_int(m.x));
            atomicMax((int*)&g_hmax[curg * DIM + lane * 2 + 1], __float_as_int(m.y));
            if (lane == 0) atomicAdd(&g_gcnt[curg], rc);
            s = make_float2(0.f, 0.f); m = make_float2(0.f, 0.f); rc = 0; curg = g;
        }
        float2 v = xc[(size_t)node * 32 + lane];
        s.x += v.x; s.y += v.y;
        m.x = fmaxf(m.x, v.x); m.y = fmaxf(m.y, v.y);
        rc++;
    }
    if (rc) {
        atomicAdd(&g_hsum[curg * DIM + lane * 2],     s.x);
        atomicAdd(&g_hsum[curg * DIM + lane * 2 + 1], s.y);
        atomicMax((int*)&g_hmax[curg * DIM + lane * 2],     __float_as_int(m.x));
        atomicMax((int*)&g_hmax[curg * DIM + lane * 2 + 1], __float_as_int(m.y));
        if (lane == 0) atomicAdd(&g_gcnt[curg], rc);
    }
}

// ---------------- classifier head ------------------------------------------
__global__ void k_mlp(const float* __restrict__ Wc1, const float* __restrict__ bc1,
                      const float* __restrict__ Wc2, const float* __restrict__ bc2,
                      float* __restrict__ out) {
    __shared__ float h[2 * DIM];
    __shared__ float r[4];
    int g = blockIdx.x, t = threadIdx.x;  // 64 threads
    float cnt = fmaxf((float)g_gcnt[g], 1.f);
    h[t]       = g_hsum[g * DIM + t] / cnt;
    h[DIM + t] = g_hmax[g * DIM + t];
    __syncthreads();
    float acc = bc1[t];
#pragma unroll 8
    for (int k = 0; k < 2 * DIM; k++) acc = fmaf(h[k], Wc1[k * DIM + t], acc);
    acc = fmaxf(acc, 0.f);
    float p0 = acc * Wc2[t * 2], p1 = acc * Wc2[t * 2 + 1];
#pragma unroll
    for (int o = 16; o; o >>= 1) {
        p0 += __shfl_down_sync(0xffffffffu, p0, o);
        p1 += __shfl_down_sync(0xffffffffu, p1, o);
    }
    if ((t & 31) == 0) { r[(t >> 5) * 2] = p0; r[(t >> 5) * 2 + 1] = p1; }
    __syncthreads();
    if (t == 0) {
        out[g * 2 + 0] = r[0] + r[2] + bc2[0];
        out[g * 2 + 1] = r[1] + r[3] + bc2[1];
    }
}

// ---------------- launcher --------------------------------------------------
extern "C" void kernel_launch(void* const* d_in, const int* in_sizes, int n_in,
                              void* d_out, int out_size) {
    const int*   tokens = (const int*)d_in[0];
    const int*   eidx   = (const int*)d_in[1];
    const int*   batch  = (const int*)d_in[2];
    const float* emb    = (const float*)d_in[3];
    const float* W0 = (const float*)d_in[4];  const float* b0 = (const float*)d_in[5];
    const float* W1 = (const float*)d_in[6];  const float* b1 = (const float*)d_in[7];
    const float* W2 = (const float*)d_in[8];  const float* b2 = (const float*)d_in[9];
    const float* Wc1 = (const float*)d_in[10]; const float* bc1 = (const float*)d_in[11];
    const float* Wc2 = (const float*)d_in[12]; const float* bc2 = (const float*)d_in[13];

    int n  = in_sizes[0];
    int e  = in_sizes[1] / 2;
    int Gn = out_size / 2;
    if (n > MAXN) n = MAXN;
    if (e > MAXE) e = MAXE;
    if (Gn > MAXG) Gn = MAXG;

    void *p_cnt, *p_hsum, *p_hmax, *p_gcnt, *p_z, *p_xa, *p_xb;
    cudaGetSymbolAddress(&p_cnt,  g_cnt);
    cudaGetSymbolAddress(&p_hsum, g_hsum);
    cudaGetSymbolAddress(&p_hmax, g_hmax);
    cudaGetSymbolAddress(&p_gcnt, g_gcnt);
    cudaGetSymbolAddress(&p_z,  g_z);
    cudaGetSymbolAddress(&p_xa, g_xa);
    cudaGetSymbolAddress(&p_xb, g_xb);
    float* Z  = (float*)p_z;
    float* XA = (float*)p_xa;
    float* XB = (float*)p_xb;

    cudaMemsetAsync(p_cnt,  0, (size_t)n * 4);
    cudaMemsetAsync(p_hsum, 0, (size_t)Gn * DIM * 4);
    cudaMemsetAsync(p_hmax, 0, (size_t)Gn * DIM * 4);  // 0.0f bits
    cudaMemsetAsync(p_gcnt, 0, (size_t)Gn * 4);

    const int* src = eidx;
    const int* dst = eidx + e;

    int eb = (e + 255) / 256;
    int nb = (n + SCAN_CHUNK - 1) / SCAN_CHUNK;
    k_count<<<eb, 256>>>(dst, e);
    k_scan1<<<nb, 256>>>(n);
    k_scan2<<<1, 1>>>(nb, n);
    k_scan3<<<nb, 256>>>(n);
    k_dinv<<<(n + 255) / 256, 256>>>(n);
    k_scatter<<<eb, 256>>>(src, dst, e);

    int gb = (n + 63) / 64;   // gemm blocks
    int wb = (n + 7) / 8;     // warp-per-node blocks (8 warps/block)

    k_gemm<<<gb, 256>>>(nullptr, tokens, emb, W0, Z, n);
    k_gather<<<wb, 256>>>(Z, b0, XA, n);
    k_gemm<<<gb, 256>>>(XA, nullptr, nullptr, W1, Z, n);
    k_gather<<<wb, 256>>>(Z, b1, XB, n);
    k_gemm<<<gb, 256>>>(XB, nullptr, nullptr, W2, Z, n);
    k_gather<<<wb, 256>>>(Z, b2, XA, n);

    int pw = (n + 31) / 32;
    k_pool<<<(pw + 7) / 8, 256>>>(XA, batch, n);
    k_mlp<<<Gn, 64>>>(Wc1, bc1, Wc2, bc2, (float*)d_out);
}

// round 6
// speedup vs baseline: 1.5854x; 1.5854x over previous
#include <cuda_runtime.h>
#include <cuda_bf16.h>
#include <cstdint>

// Problem constants (fixed shapes for this problem)
#define MAXN 100000
#define MAXE 1600000
#define DIM  64
#define MAXG 512
#define SCAN_CHUNK 1024

// ---------------- scratch (static device globals; no allocation allowed) ----
__device__ int   g_cnt[MAXN];          // in-degree counts (excl self loop)
__device__ int   g_rowptr[MAXN + 1];   // CSR row pointers (by dst)
__device__ int   g_cursor[MAXN];       // scatter cursors
__device__ float g_dinv[MAXN];         // deg^-0.5 (deg incl self loop)
__device__ int   g_esrc[MAXE];         // CSR column (src) indices
__device__ int   g_bsum[(MAXN + SCAN_CHUNK - 1) / SCAN_CHUNK + 1];
__device__ float g_z[(size_t)MAXN * DIM];   // z = dinv * (x @ W), fp32
__device__ float g_xa[(size_t)MAXN * DIM];  // feature ping
__device__ float g_xb[(size_t)MAXN * DIM];  // feature pong
__device__ float g_hsum[MAXG * DIM];
__device__ float g_hmax[MAXG * DIM];
__device__ int   g_gcnt[MAXG];

// ---------------- small helpers --------------------------------------------
__device__ __forceinline__ void fma2(unsigned long long& d, unsigned long long a,
                                     unsigned long long b) {
    asm("fma.rn.f32x2 %0, %1, %2, %0;" : "+l"(d) : "l"(a), "l"(b));
}
__device__ __forceinline__ unsigned long long pack2(float x) {
    unsigned long long r;
    asm("mov.b64 %0, {%1, %1};" : "=l"(r) : "f"(x));
    return r;
}
__device__ __forceinline__ float2 unpack2(unsigned long long v) {
    float2 f;
    asm("mov.b64 {%0, %1}, %2;" : "=f"(f.x), "=f"(f.y) : "l"(v));
    return f;
}

// ---------------- CSR build ------------------------------------------------
__global__ void k_count(const int* __restrict__ dst, int e) {
    int i = blockIdx.x * blockDim.x + threadIdx.x;
    if (i < e) atomicAdd(&g_cnt[dst[i]], 1);
}

__global__ void k_scan1(int n) {  // per-1024-chunk sums
    int t = threadIdx.x;
    int base = blockIdx.x * SCAN_CHUNK + t * 4;
    int s = 0;
#pragma unroll
    for (int j = 0; j < 4; j++) if (base + j < n) s += g_cnt[base + j];
#pragma unroll
    for (int o = 16; o; o >>= 1) s += __shfl_down_sync(0xffffffffu, s, o);
    __shared__ int ws[8];
    if ((t & 31) == 0) ws[t >> 5] = s;
    __syncthreads();
    if (t == 0) {
        int tot = 0;
#pragma unroll
        for (int i = 0; i < 8; i++) tot += ws[i];
        g_bsum[blockIdx.x] = tot;
    }
}

__global__ void k_scan2(int nb, int n) {  // tiny serial scan of chunk sums
    int run = 0;
    for (int i = 0; i < nb; i++) { int v = g_bsum[i]; g_bsum[i] = run; run += v; }
    g_rowptr[n] = run;
}

__global__ void k_scan3(int n) {  // per-chunk exclusive scan -> rowptr/cursor
    int t = threadIdx.x;
    int lane = t & 31, wid = t >> 5;
    int base = blockIdx.x * SCAN_CHUNK + t * 4;
    int c0 = (base + 0 < n) ? g_cnt[base + 0] : 0;
    int c1 = (base + 1 < n) ? g_cnt[base + 1] : 0;
    int c2 = (base + 2 < n) ? g_cnt[base + 2] : 0;
    int c3 = (base + 3 < n) ? g_cnt[base + 3] : 0;
    int ts = c0 + c1 + c2 + c3;
    int x = ts;
#pragma unroll
    for (int o = 1; o < 32; o <<= 1) {
        int y = __shfl_up_sync(0xffffffffu, x, o);
        if (lane >= o) x += y;
    }
    int wex = x - ts;  // exclusive within warp
    __shared__ int warpsums[8];
    if (lane == 31) warpsums[wid] = x;
    __syncthreads();
    int woff = 0;
    for (int i = 0; i < wid; i++) woff += warpsums[i];
    int off = g_bsum[blockIdx.x] + woff + wex;
    if (base + 0 < n) { g_rowptr[base + 0] = off;             g_cursor[base + 0] = off; }
    if (base + 1 < n) { g_rowptr[base + 1] = off + c0;        g_cursor[base + 1] = off + c0; }
    if (base + 2 < n) { g_rowptr[base + 2] = off + c0 + c1;   g_cursor[base + 2] = off + c0 + c1; }
    if (base + 3 < n) { g_rowptr[base + 3] = off + c0 + c1 + c2; g_cursor[base + 3] = off + c0 + c1 + c2; }
}

__global__ void k_dinv(int n) {
    int i = blockIdx.x * blockDim.x + threadIdx.x;
    if (i < n) g_dinv[i] = rsqrtf((float)(g_cnt[i] + 1));  // +1 self loop
}

__global__ void k_scatter(const int* __restrict__ src, const int* __restrict__ dst, int e) {
    int i = blockIdx.x * blockDim.x + threadIdx.x;
    if (i < e) {
        int d = dst[i];
        int p = atomicAdd(&g_cursor[d], 1);
        g_esrc[p] = src[i];
    }
}

// ---------------- fused GEMM: z = dinv[i] * (x_i @ W) ----------------------
// block = 256 threads; block tile = 256 rows x 64 cols;
// thread = 4 rows x 16 cols, accumulators packed as f32x2 (exact fp32 math).
__global__ void __launch_bounds__(256, 2)
k_gemm(const float* __restrict__ X, const int* __restrict__ tokens,
       const float* __restrict__ emb, const float* __restrict__ W,
       float* __restrict__ Z, int n) {
    __shared__ float Ws[DIM * DIM];
    int t = threadIdx.x;
    for (int i = t; i < DIM * DIM / 4; i += 256)
        ((float4*)Ws)[i] = ((const float4*)W)[i];
    __syncthreads();

    int rg = blockIdx.x * 64 + (t >> 2);   // row-group of 4 rows
    int r0 = rg * 4;
    if (r0 >= n) return;
    int cg = (t & 3) * 16;                 // first column of this thread

    const float* xr[4];
#pragma unroll
    for (int r = 0; r < 4; r++) {
        int rowc = r0 + r;
        int rr = rowc < n ? rowc : (n - 1);
        xr[r] = tokens ? (emb + (size_t)__ldg(tokens + rr) * DIM)
                       : (X + (size_t)rr * DIM);
    }

    unsigned long long acc[4][8];
#pragma unroll
    for (int r = 0; r < 4; r++)
#pragma unroll
        for (int j = 0; j < 8; j++) acc[r][j] = 0ull;

#pragma unroll
    for (int k = 0; k < DIM; k += 4) {
        float4 xv0 = *(const float4*)(xr[0] + k);
        float4 xv1 = *(const float4*)(xr[1] + k);
        float4 xv2 = *(const float4*)(xr[2] + k);
        float4 xv3 = *(const float4*)(xr[3] + k);
#pragma unroll
        for (int kk = 0; kk < 4; kk++) {
            const ulonglong2* wp = (const ulonglong2*)(Ws + (k + kk) * DIM + cg);
            ulonglong2 wa = wp[0], wb = wp[1], wc = wp[2], wd = wp[3];
            unsigned long long x0 = pack2((&xv0.x)[kk]);
            unsigned long long x1 = pack2((&xv1.x)[kk]);
            unsigned long long x2 = pack2((&xv2.x)[kk]);
            unsigned long long x3 = pack2((&xv3.x)[kk]);
            fma2(acc[0][0], x0, wa.x); fma2(acc[0][1], x0, wa.y);
            fma2(acc[0][2], x0, wb.x); fma2(acc[0][3], x0, wb.y);
            fma2(acc[0][4], x0, wc.x); fma2(acc[0][5], x0, wc.y);
            fma2(acc[0][6], x0, wd.x); fma2(acc[0][7], x0, wd.y);
            fma2(acc[1][0], x1, wa.x); fma2(acc[1][1], x1, wa.y);
            fma2(acc[1][2], x1, wb.x); fma2(acc[1][3], x1, wb.y);
            fma2(acc[1][4], x1, wc.x); fma2(acc[1][5], x1, wc.y);
            fma2(acc[1][6], x1, wd.x); fma2(acc[1][7], x1, wd.y);
            fma2(acc[2][0], x2, wa.x); fma2(acc[2][1], x2, wa.y);
            fma2(acc[2][2], x2, wb.x); fma2(acc[2][3], x2, wb.y);
            fma2(acc[2][4], x2, wc.x); fma2(acc[2][5], x2, wc.y);
            fma2(acc[2][6], x2, wd.x); fma2(acc[2][7], x2, wd.y);
            fma2(acc[3][0], x3, wa.x); fma2(acc[3][1], x3, wa.y);
            fma2(acc[3][2], x3, wb.x); fma2(acc[3][3], x3, wb.y);
            fma2(acc[3][4], x3, wc.x); fma2(acc[3][5], x3, wc.y);
            fma2(acc[3][6], x3, wd.x); fma2(acc[3][7], x3, wd.y);
        }
    }

#pragma unroll
    for (int r = 0; r < 4; r++) {
        int rowc = r0 + r;
        if (rowc >= n) break;
        float dv = g_dinv[rowc];
        float* zr = Z + (size_t)rowc * DIM + cg;
#pragma unroll
        for (int j = 0; j < 8; j += 2) {
            float2 f0 = unpack2(acc[r][j]);
            float2 f1 = unpack2(acc[r][j + 1]);
            float4 o;
            o.x = f0.x * dv; o.y = f0.y * dv;
            o.z = f1.x * dv; o.w = f1.y * dv;
            *(float4*)(zr + j * 2) = o;
        }
    }
}

// ---------------- gather: x_out[i] = relu(dinv[i]*(z[i] + sum z[src]) + b) --
// warp per destination node; lane covers 2 feature dims as float2
__global__ void k_gather(const float* __restrict__ Z, const float* __restrict__ b,
                         float* __restrict__ Xo, int n) {
    int w = (int)((blockIdx.x * blockDim.x + threadIdx.x) >> 5);
    if (w >= n) return;
    int lane = threadIdx.x & 31;
    int beg = g_rowptr[w], end = g_rowptr[w + 1];
    const float2* zc = (const float2*)Z;        // node row = 32 float2
    float2 acc = zc[(size_t)w * 32 + lane];     // self loop
    for (int e0 = beg; e0 < end; e0 += 32) {
        int c = end - e0; if (c > 32) c = 32;
        int s = (lane < c) ? g_esrc[e0 + lane] : 0;
        int j = 0;
        for (; j + 4 <= c; j += 4) {
            int s0 = __shfl_sync(0xffffffffu, s, j);
            int s1 = __shfl_sync(0xffffffffu, s, j + 1);
            int s2 = __shfl_sync(0xffffffffu, s, j + 2);
            int s3 = __shfl_sync(0xffffffffu, s, j + 3);
            float2 v0 = zc[(size_t)s0 * 32 + lane];
            float2 v1 = zc[(size_t)s1 * 32 + lane];
            float2 v2 = zc[(size_t)s2 * 32 + lane];
            float2 v3 = zc[(size_t)s3 * 32 + lane];
            acc.x += (v0.x + v1.x) + (v2.x + v3.x);
            acc.y += (v0.y + v1.y) + (v2.y + v3.y);
        }
        for (; j < c; j++) {
            int sj = __shfl_sync(0xffffffffu, s, j);
            float2 v = zc[(size_t)sj * 32 + lane];
            acc.x += v.x; acc.y += v.y;
        }
    }
    float dv = g_dinv[w];
    int col = lane * 2;
    float2 o;
    o.x = fmaxf(fmaf(dv, acc.x, __ldg(b + col)),     0.f);
    o.y = fmaxf(fmaf(dv, acc.y, __ldg(b + col + 1)), 0.f);
    ((float2*)Xo)[(size_t)w * 32 + lane] = o;
}

// ---------------- pooling (batch sorted): run-accumulate, flush on boundary -
__global__ void k_pool(const float* __restrict__ X, const int* __restrict__ batch, int n) {
    int w = (int)((blockIdx.x * blockDim.x + threadIdx.x) >> 5);
    int lane = threadIdx.x & 31;
    int base = w * 32;
    if (base >= n) return;
    int myb = (base + lane < n) ? batch[base + lane] : 0;
    const float2* xc = (const float2*)X;
    float2 s = make_float2(0.f, 0.f), m = make_float2(0.f, 0.f);
    int curg = __shfl_sync(0xffffffffu, myb, 0);
    int rc = 0;
    for (int j = 0; j < 32; j++) {
        int node = base + j;
        if (node >= n) break;
        int g = __shfl_sync(0xffffffffu, myb, j);
        if (g != curg) {
            atomicAdd(&g_hsum[curg * DIM + lane * 2],     s.x);
            atomicAdd(&g_hsum[curg * DIM + lane * 2 + 1], s.y);
            atomicMax((int*)&g_hmax[curg * DIM + lane * 2],     __float_as_int(m.x));
            atomicMax((int*)&g_hmax[curg * DIM + lane * 2 + 1], __float_as_int(m.y));
            if (lane == 0) atomicAdd(&g_gcnt[curg], rc);
            s = make_float2(0.f, 0.f); m = make_float2(0.f, 0.f); rc = 0; curg = g;
        }
        float2 v = xc[(size_t)node * 32 + lane];
        s.x += v.x; s.y += v.y;
        m.x = fmaxf(m.x, v.x); m.y = fmaxf(m.y, v.y);
        rc++;
    }
    if (rc) {
        atomicAdd(&g_hsum[curg * DIM + lane * 2],     s.x);
        atomicAdd(&g_hsum[curg * DIM + lane * 2 + 1], s.y);
        atomicMax((int*)&g_hmax[curg * DIM + lane * 2],     __float_as_int(m.x));
        atomicMax((int*)&g_hmax[curg * DIM + lane * 2 + 1], __float_as_int(m.y));
        if (lane == 0) atomicAdd(&g_gcnt[curg], rc);
    }
}

// ---------------- classifier head ------------------------------------------
__global__ void k_mlp(const float* __restrict__ Wc1, const float* __restrict__ bc1,
                      const float* __restrict__ Wc2, const float* __restrict__ bc2,
                      float* __restrict__ out) {
    __shared__ float h[2 * DIM];
    __shared__ float r[4];
    int g = blockIdx.x, t = threadIdx.x;  // 64 threads
    float cnt = fmaxf((float)g_gcnt[g], 1.f);
    h[t]       = g_hsum[g * DIM + t] / cnt;
    h[DIM + t] = g_hmax[g * DIM + t];
    __syncthreads();
    float acc = bc1[t];
#pragma unroll 8
    for (int k = 0; k < 2 * DIM; k++) acc = fmaf(h[k], Wc1[k * DIM + t], acc);
    acc = fmaxf(acc, 0.f);
    float p0 = acc * Wc2[t * 2], p1 = acc * Wc2[t * 2 + 1];
#pragma unroll
    for (int o = 16; o; o >>= 1) {
        p0 += __shfl_down_sync(0xffffffffu, p0, o);
        p1 += __shfl_down_sync(0xffffffffu, p1, o);
    }
    if ((t & 31) == 0) { r[(t >> 5) * 2] = p0; r[(t >> 5) * 2 + 1] = p1; }
    __syncthreads();
    if (t == 0) {
        out[g * 2 + 0] = r[0] + r[2] + bc2[0];
        out[g * 2 + 1] = r[1] + r[3] + bc2[1];
    }
}

// ---------------- launcher --------------------------------------------------
extern "C" void kernel_launch(void* const* d_in, const int* in_sizes, int n_in,
                              void* d_out, int out_size) {
    const int*   tokens = (const int*)d_in[0];
    const int*   eidx   = (const int*)d_in[1];
    const int*   batch  = (const int*)d_in[2];
    const float* emb    = (const float*)d_in[3];
    const float* W0 = (const float*)d_in[4];  const float* b0 = (const float*)d_in[5];
    const float* W1 = (const float*)d_in[6];  const float* b1 = (const float*)d_in[7];
    const float* W2 = (const float*)d_in[8];  const float* b2 = (const float*)d_in[9];
    const float* Wc1 = (const float*)d_in[10]; const float* bc1 = (const float*)d_in[11];
    const float* Wc2 = (const float*)d_in[12]; const float* bc2 = (const float*)d_in[13];

    int n  = in_sizes[0];
    int e  = in_sizes[1] / 2;
    int Gn = out_size / 2;
    if (n > MAXN) n = MAXN;
    if (e > MAXE) e = MAXE;
    if (Gn > MAXG) Gn = MAXG;

    void *p_cnt, *p_hsum, *p_hmax, *p_gcnt, *p_z, *p_xa, *p_xb;
    cudaGetSymbolAddress(&p_cnt,  g_cnt);
    cudaGetSymbolAddress(&p_hsum, g_hsum);
    cudaGetSymbolAddress(&p_hmax, g_hmax);
    cudaGetSymbolAddress(&p_gcnt, g_gcnt);
    cudaGetSymbolAddress(&p_z,  g_z);
    cudaGetSymbolAddress(&p_xa, g_xa);
    cudaGetSymbolAddress(&p_xb, g_xb);
    float* Z  = (float*)p_z;
    float* XA = (float*)p_xa;
    float* XB = (float*)p_xb;

    cudaMemsetAsync(p_cnt,  0, (size_t)n * 4);
    cudaMemsetAsync(p_hsum, 0, (size_t)Gn * DIM * 4);
    cudaMemsetAsync(p_hmax, 0, (size_t)Gn * DIM * 4);  // 0.0f bits
    cudaMemsetAsync(p_gcnt, 0, (size_t)Gn * 4);

    const int* src = eidx;
    const int* dst = eidx + e;

    int eb = (e + 255) / 256;
    int nb = (n + SCAN_CHUNK - 1) / SCAN_CHUNK;
    k_count<<<eb, 256>>>(dst, e);
    k_scan1<<<nb, 256>>>(n);
    k_scan2<<<1, 1>>>(nb, n);
    k_scan3<<<nb, 256>>>(n);
    k_dinv<<<(n + 255) / 256, 256>>>(n);
    k_scatter<<<eb, 256>>>(src, dst, e);

    int gb = (n + 255) / 256;  // gemm blocks (256 rows per block)
    int wb = (n + 7) / 8;      // warp-per-node blocks (8 warps/block)

    k_gemm<<<gb, 256>>>(nullptr, tokens, emb, W0, Z, n);
    k_gather<<<wb, 256>>>(Z, b0, XA, n);
    k_gemm<<<gb, 256>>>(XA, nullptr, nullptr, W1, Z, n);
    k_gather<<<wb, 256>>>(Z, b1, XB, n);
    k_gemm<<<gb, 256>>>(XB, nullptr, nullptr, W2, Z, n);
    k_gather<<<wb, 256>>>(Z, b2, XA, n);

    int pw = (n + 31) / 32;
    k_pool<<<(pw + 7) / 8, 256>>>(XA, batch, n);
    k_mlp<<<Gn, 64>>>(Wc1, bc1, Wc2, bc2, (float*)d_out);
}